// round 13
// baseline (speedup 1.0000x reference)
#include <cuda_runtime.h>
#include <math.h>

// Problem dims
#define B_   256
#define T_   168
#define LAG_ 168
#define LAT_ 128
#define WS_  64
#define H_   1024

// Step-GEMM tiling
#define BM   32
#define BH   64
#define BKQ  16
#define NTH  128

// Scratch: hidden states hs[0..T], hs[0] = h0 from encoder.
__device__ float g_hs[(T_ + 1) * B_ * H_];
__device__ float g_e1[B_ * 64];
__device__ float g_e2[B_ * LAT_];

typedef unsigned long long ull;

__device__ __forceinline__ ull pk2(float x, float y) {
    ull r; asm("mov.b64 %0, {%1, %2};" : "=l"(r) : "f"(x), "f"(y)); return r;
}
__device__ __forceinline__ void up2(ull v, float& x, float& y) {
    asm("mov.b64 {%0, %1}, %2;" : "=f"(x), "=f"(y) : "l"(v));
}
// packed f32x2 FMA: d = a*b + d (lanewise). Only reachable via PTX fma.rn.f32x2.
__device__ __forceinline__ void fma2(ull& d, ull a, ull b) {
    asm("fma.rn.f32x2 %0, %1, %2, %0;" : "+l"(d) : "l"(a), "l"(b));
}

// ---------------- Encoder MLP (tiny) ----------------

__global__ void enc1_kernel(const float* __restrict__ lag,
                            const float* __restrict__ W1,
                            const float* __restrict__ b1) {
    int idx = blockIdx.x * blockDim.x + threadIdx.x;
    if (idx >= B_ * 64) return;
    int b = idx >> 6, o = idx & 63;
    const float* lr = lag + (size_t)b * LAG_;
    const float* wr = W1 + (size_t)o * LAG_;
    float s = b1[o];
#pragma unroll 4
    for (int k = 0; k < LAG_; k++) s = fmaf(lr[k], wr[k], s);
    g_e1[idx] = (s >= 0.f) ? s : 0.01f * s;
}

__global__ void enc2_kernel(const float* __restrict__ W2,
                            const float* __restrict__ b2) {
    int idx = blockIdx.x * blockDim.x + threadIdx.x;
    if (idx >= B_ * LAT_) return;
    int b = idx / LAT_, o = idx % LAT_;
    const float* er = g_e1 + (size_t)b * 64;
    const float* wr = W2 + (size_t)o * 64;
    float s = b2[o];
#pragma unroll 8
    for (int k = 0; k < 64; k++) s = fmaf(er[k], wr[k], s);
    g_e2[idx] = (s >= 0.f) ? s : 0.01f * s;
}

__global__ void enc3_kernel(const float* __restrict__ W3,
                            const float* __restrict__ b3) {
    int idx = blockIdx.x * blockDim.x + threadIdx.x;
    if (idx >= B_ * H_) return;
    int b = idx >> 10, o = idx & (H_ - 1);
    const float* er = g_e2 + (size_t)b * LAT_;
    const float* wr = W3 + (size_t)o * LAT_;
    float s = b3[o];
#pragma unroll 8
    for (int k = 0; k < LAT_; k++) s = fmaf(er[k], wr[k], s);
    g_hs[idx] = s;   // hs[0] = h0
}

// ---------------- GRU step kernel ----------------
// One launch per timestep. Each CTA computes an h-tile [BM x BH] of h_new.
// It accumulates the three gate pre-activations (r, z combined over both
// phases; hn and inn kept separate as the reference requires) and applies
// the full GRU gate math in the epilogue.

struct Stage {
    float4 a;
    float4 b[6];
};

__device__ __forceinline__ void fetch_stage(Stage& st,
                                            const float* __restrict__ Ap, int lda,
                                            const float* __restrict__ Wp, int ldw,
                                            int k0, int m0, int h0, int tid) {
    int row = tid >> 2;            // 0..31
    int kc  = (tid & 3) << 2;      // 0,4,8,12
    st.a = *(const float4*)(Ap + (size_t)(m0 + row) * lda + k0 + kc);
#pragma unroll
    for (int g = 0; g < 3; g++)
#pragma unroll
        for (int r = 0; r < 2; r++) {
            int hh = row + (r << 5);   // 0..63
            st.b[g * 2 + r] =
                *(const float4*)(Wp + (size_t)(h0 + g * H_ + hh) * ldw + k0 + kc);
        }
}

__device__ __forceinline__ void store_stage(const Stage& st, int tid,
                                            float (&sA)[BKQ][36],
                                            float (&sB)[3][BKQ][68]) {
    int row = tid >> 2;
    int kc  = (tid & 3) << 2;
    sA[kc + 0][row] = st.a.x;
    sA[kc + 1][row] = st.a.y;
    sA[kc + 2][row] = st.a.z;
    sA[kc + 3][row] = st.a.w;
#pragma unroll
    for (int g = 0; g < 3; g++)
#pragma unroll
        for (int r = 0; r < 2; r++) {
            int hh = row + (r << 5);
            float4 v = st.b[g * 2 + r];
            sB[g][kc + 0][hh] = v.x;
            sB[g][kc + 1][hh] = v.y;
            sB[g][kc + 2][hh] = v.z;
            sB[g][kc + 3][hh] = v.w;
        }
}

__device__ __forceinline__ void compute_tile(const float (&sA)[BKQ][36],
                                             const float (&sB)[3][BKQ][68],
                                             int m_off, int h_off,
                                             ull (&aR)[4][2], ull (&aZ)[4][2],
                                             ull (&aN)[4][2]) {
#pragma unroll
    for (int k = 0; k < BKQ; k++) {
        float4 a = *(const float4*)&sA[k][m_off];
        ull pa0 = pk2(a.x, a.x);
        ull pa1 = pk2(a.y, a.y);
        ull pa2 = pk2(a.z, a.z);
        ull pa3 = pk2(a.w, a.w);
        ulonglong2 bR = *(const ulonglong2*)&sB[0][k][h_off];
        ulonglong2 bZ = *(const ulonglong2*)&sB[1][k][h_off];
        ulonglong2 bN = *(const ulonglong2*)&sB[2][k][h_off];

        fma2(aR[0][0], pa0, bR.x); fma2(aR[0][1], pa0, bR.y);
        fma2(aR[1][0], pa1, bR.x); fma2(aR[1][1], pa1, bR.y);
        fma2(aR[2][0], pa2, bR.x); fma2(aR[2][1], pa2, bR.y);
        fma2(aR[3][0], pa3, bR.x); fma2(aR[3][1], pa3, bR.y);

        fma2(aZ[0][0], pa0, bZ.x); fma2(aZ[0][1], pa0, bZ.y);
        fma2(aZ[1][0], pa1, bZ.x); fma2(aZ[1][1], pa1, bZ.y);
        fma2(aZ[2][0], pa2, bZ.x); fma2(aZ[2][1], pa2, bZ.y);
        fma2(aZ[3][0], pa3, bZ.x); fma2(aZ[3][1], pa3, bZ.y);

        fma2(aN[0][0], pa0, bN.x); fma2(aN[0][1], pa0, bN.y);
        fma2(aN[1][0], pa1, bN.x); fma2(aN[1][1], pa1, bN.y);
        fma2(aN[2][0], pa2, bN.x); fma2(aN[2][1], pa2, bN.y);
        fma2(aN[3][0], pa3, bN.x); fma2(aN[3][1], pa3, bN.y);
    }
}

__global__ void __launch_bounds__(NTH, 1)
gru_step_kernel(const float* __restrict__ curr, int t,
                const float* __restrict__ Wih, const float* __restrict__ Whh,
                const float* __restrict__ bih, const float* __restrict__ bhh) {
    __shared__ float sA[2][BKQ][36];
    __shared__ float sB[2][3][BKQ][68];

    const float* x_t    = curr + (size_t)t * B_ * WS_;
    const float* h_prev = g_hs + (size_t)t * B_ * H_;
    float*       h_out  = g_hs + (size_t)(t + 1) * B_ * H_;

    const int tid   = threadIdx.x;
    const int h0    = blockIdx.x * BH;
    const int m0    = blockIdx.y * BM;
    const int m_off = (tid >> 4) << 2;   // 0..28
    const int h_off = (tid & 15) << 2;   // 0..60

    ull aR[4][2], aZ[4][2], aN[4][2], aI[4][2];
#pragma unroll
    for (int i = 0; i < 4; i++) {
        aR[i][0] = aR[i][1] = 0ULL;
        aZ[i][0] = aZ[i][1] = 0ULL;
        aN[i][0] = aN[i][1] = 0ULL;
        aI[i][0] = aI[i][1] = 0ULL;
    }

    Stage st;

    // ---- Phase 0: recurrent GEMM over K = H (Whh) -> aR, aZ, aN ----
    fetch_stage(st, h_prev, H_, Whh, H_, 0, m0, h0, tid);
    store_stage(st, tid, sA[0], sB[0]);
    __syncthreads();
#pragma unroll 1
    for (int k0 = 0; k0 < H_; k0 += BKQ) {
        int buf = (k0 >> 4) & 1;
        bool more = (k0 + BKQ) < H_;
        if (more) fetch_stage(st, h_prev, H_, Whh, H_, k0 + BKQ, m0, h0, tid);
        compute_tile(sA[buf], sB[buf], m_off, h_off, aR, aZ, aN);
        if (more) store_stage(st, tid, sA[buf ^ 1], sB[buf ^ 1]);
        __syncthreads();
    }

    // ---- Phase 1: input GEMM over K = WS (Wih) -> aR, aZ, aI ----
    fetch_stage(st, x_t, WS_, Wih, WS_, 0, m0, h0, tid);
    store_stage(st, tid, sA[0], sB[0]);
    __syncthreads();
#pragma unroll 1
    for (int k0 = 0; k0 < WS_; k0 += BKQ) {
        int buf = (k0 >> 4) & 1;
        bool more = (k0 + BKQ) < WS_;
        if (more) fetch_stage(st, x_t, WS_, Wih, WS_, k0 + BKQ, m0, h0, tid);
        compute_tile(sA[buf], sB[buf], m_off, h_off, aR, aZ, aI);
        if (more) store_stage(st, tid, sA[buf ^ 1], sB[buf ^ 1]);
        __syncthreads();
    }

    // ---- Epilogue: GRU gates + blend ----
#pragma unroll
    for (int i = 0; i < 4; i++) {
        int m = m0 + m_off + i;
#pragma unroll
        for (int p = 0; p < 2; p++) {
            float gr[2], gz[2], gn[2], gi[2];
            up2(aR[i][p], gr[0], gr[1]);
            up2(aZ[i][p], gz[0], gz[1]);
            up2(aN[i][p], gn[0], gn[1]);
            up2(aI[i][p], gi[0], gi[1]);
#pragma unroll
            for (int q = 0; q < 2; q++) {
                int j = h0 + h_off + 2 * p + q;
                float pre_r = gr[q] + bih[j] + bhh[j];
                float pre_z = gz[q] + bih[H_ + j] + bhh[H_ + j];
                float hn    = gn[q] + bhh[2 * H_ + j];
                float inn   = gi[q] + bih[2 * H_ + j];
                float r = 1.f / (1.f + expf(-pre_r));
                float z = 1.f / (1.f + expf(-pre_z));
                float n = tanhf(inn + r * hn);
                float hp = h_prev[(size_t)m * H_ + j];
                h_out[(size_t)m * H_ + j] = (1.f - z) * n + z * hp;
            }
        }
    }
}

// ---------------- Output projection: preds[b][t] = hs[t+1][b] . Wo + bo ----------------

__global__ void pred_kernel(const float* __restrict__ Wo,
                            const float* __restrict__ bo,
                            float* __restrict__ out) {
    int gw = (blockIdx.x * blockDim.x + threadIdx.x) >> 5;
    int lane = threadIdx.x & 31;
    if (gw >= T_ * B_) return;
    int t = gw / B_, b = gw % B_;
    const float* h = g_hs + ((size_t)(t + 1) * B_ + b) * H_;
    float s = 0.f;
#pragma unroll 8
    for (int k = lane; k < H_; k += 32) s = fmaf(h[k], Wo[k], s);
#pragma unroll
    for (int o = 16; o; o >>= 1) s += __shfl_xor_sync(0xffffffffu, s, o);
    if (lane == 0) out[(size_t)b * T_ + t] = s + bo[0];
}

// ---------------- Launch ----------------

extern "C" void kernel_launch(void* const* d_in, const int* in_sizes, int n_in,
                              void* d_out, int out_size) {
    const float* lag  = (const float*)d_in[0];
    const float* curr = (const float*)d_in[1];
    const float* W1   = (const float*)d_in[2];
    const float* b1   = (const float*)d_in[3];
    const float* W2   = (const float*)d_in[4];
    const float* b2   = (const float*)d_in[5];
    const float* W3   = (const float*)d_in[6];
    const float* b3   = (const float*)d_in[7];
    const float* Wih  = (const float*)d_in[8];
    const float* Whh  = (const float*)d_in[9];
    const float* bih  = (const float*)d_in[10];
    const float* bhh  = (const float*)d_in[11];
    const float* Wo   = (const float*)d_in[12];
    const float* bo   = (const float*)d_in[13];
    float* out = (float*)d_out;

    enc1_kernel<<<(B_ * 64 + 255) / 256, 256>>>(lag, W1, b1);
    enc2_kernel<<<(B_ * LAT_ + 255) / 256, 256>>>(W2, b2);
    enc3_kernel<<<(B_ * H_ + 255) / 256, 256>>>(W3, b3);

    dim3 grid(H_ / BH, B_ / BM);   // (16, 8) = 128 CTAs
    for (int t = 0; t < T_; t++) {
        gru_step_kernel<<<grid, NTH>>>(curr, t, Wih, Whh, bih, bhh);
    }

    int warps = T_ * B_;
    pred_kernel<<<(warps * 32 + 255) / 256, 256>>>(Wo, bo, out);
}

// round 14
// speedup vs baseline: 1.0007x; 1.0007x over previous
#include <cuda_runtime.h>
#include <math.h>

// Problem dims
#define B_   256
#define T_   168
#define LAG_ 168
#define LAT_ 128
#define WS_  64
#define H_   1024

// Step-GEMM tiling
#define BM   32
#define BH   64
#define BKQ  16
#define NTH  128

// Scratch: hidden states hs[0..T], hs[0] = h0 from encoder.
__device__ float g_hs[(T_ + 1) * B_ * H_];
__device__ float g_e1[B_ * 64];
__device__ float g_e2[B_ * LAT_];

typedef unsigned long long ull;

__device__ __forceinline__ ull pk2(float x, float y) {
    ull r; asm("mov.b64 %0, {%1, %2};" : "=l"(r) : "f"(x), "f"(y)); return r;
}
__device__ __forceinline__ void up2(ull v, float& x, float& y) {
    asm("mov.b64 {%0, %1}, %2;" : "=f"(x), "=f"(y) : "l"(v));
}
// packed f32x2 FMA: d = a*b + d (lanewise). Only reachable via PTX fma.rn.f32x2.
__device__ __forceinline__ void fma2(ull& d, ull a, ull b) {
    asm("fma.rn.f32x2 %0, %1, %2, %0;" : "+l"(d) : "l"(a), "l"(b));
}

// ---------------- Encoder MLP (tiny) ----------------

__global__ void enc1_kernel(const float* __restrict__ lag,
                            const float* __restrict__ W1,
                            const float* __restrict__ b1) {
    int idx = blockIdx.x * blockDim.x + threadIdx.x;
    if (idx >= B_ * 64) return;
    int b = idx >> 6, o = idx & 63;
    const float* lr = lag + (size_t)b * LAG_;
    const float* wr = W1 + (size_t)o * LAG_;
    float s = b1[o];
#pragma unroll 4
    for (int k = 0; k < LAG_; k++) s = fmaf(lr[k], wr[k], s);
    g_e1[idx] = (s >= 0.f) ? s : 0.01f * s;
}

__global__ void enc2_kernel(const float* __restrict__ W2,
                            const float* __restrict__ b2) {
    int idx = blockIdx.x * blockDim.x + threadIdx.x;
    if (idx >= B_ * LAT_) return;
    int b = idx / LAT_, o = idx % LAT_;
    const float* er = g_e1 + (size_t)b * 64;
    const float* wr = W2 + (size_t)o * 64;
    float s = b2[o];
#pragma unroll 8
    for (int k = 0; k < 64; k++) s = fmaf(er[k], wr[k], s);
    g_e2[idx] = (s >= 0.f) ? s : 0.01f * s;
}

__global__ void enc3_kernel(const float* __restrict__ W3,
                            const float* __restrict__ b3) {
    int idx = blockIdx.x * blockDim.x + threadIdx.x;
    if (idx >= B_ * H_) return;
    int b = idx >> 10, o = idx & (H_ - 1);
    const float* er = g_e2 + (size_t)b * LAT_;
    const float* wr = W3 + (size_t)o * LAT_;
    float s = b3[o];
#pragma unroll 8
    for (int k = 0; k < LAT_; k++) s = fmaf(er[k], wr[k], s);
    g_hs[idx] = s;   // hs[0] = h0
}

// ---------------- GRU step kernel ----------------
// One launch per timestep. Each CTA computes an h-tile [BM x BH] of h_new.
// It accumulates the three gate pre-activations (r, z combined over both
// phases; hn and inn kept separate as the reference requires) and applies
// the full GRU gate math in the epilogue.

struct Stage {
    float4 a;
    float4 b[6];
};

__device__ __forceinline__ void fetch_stage(Stage& st,
                                            const float* __restrict__ Ap, int lda,
                                            const float* __restrict__ Wp, int ldw,
                                            int k0, int m0, int h0, int tid) {
    int row = tid >> 2;            // 0..31
    int kc  = (tid & 3) << 2;      // 0,4,8,12
    st.a = *(const float4*)(Ap + (size_t)(m0 + row) * lda + k0 + kc);
#pragma unroll
    for (int g = 0; g < 3; g++)
#pragma unroll
        for (int r = 0; r < 2; r++) {
            int hh = row + (r << 5);   // 0..63
            st.b[g * 2 + r] =
                *(const float4*)(Wp + (size_t)(h0 + g * H_ + hh) * ldw + k0 + kc);
        }
}

__device__ __forceinline__ void store_stage(const Stage& st, int tid,
                                            float (&sA)[BKQ][36],
                                            float (&sB)[3][BKQ][68]) {
    int row = tid >> 2;
    int kc  = (tid & 3) << 2;
    sA[kc + 0][row] = st.a.x;
    sA[kc + 1][row] = st.a.y;
    sA[kc + 2][row] = st.a.z;
    sA[kc + 3][row] = st.a.w;
#pragma unroll
    for (int g = 0; g < 3; g++)
#pragma unroll
        for (int r = 0; r < 2; r++) {
            int hh = row + (r << 5);
            float4 v = st.b[g * 2 + r];
            sB[g][kc + 0][hh] = v.x;
            sB[g][kc + 1][hh] = v.y;
            sB[g][kc + 2][hh] = v.z;
            sB[g][kc + 3][hh] = v.w;
        }
}

__device__ __forceinline__ void compute_tile(const float (&sA)[BKQ][36],
                                             const float (&sB)[3][BKQ][68],
                                             int m_off, int h_off,
                                             ull (&aR)[4][2], ull (&aZ)[4][2],
                                             ull (&aN)[4][2]) {
#pragma unroll
    for (int k = 0; k < BKQ; k++) {
        float4 a = *(const float4*)&sA[k][m_off];
        ull pa0 = pk2(a.x, a.x);
        ull pa1 = pk2(a.y, a.y);
        ull pa2 = pk2(a.z, a.z);
        ull pa3 = pk2(a.w, a.w);
        ulonglong2 bR = *(const ulonglong2*)&sB[0][k][h_off];
        ulonglong2 bZ = *(const ulonglong2*)&sB[1][k][h_off];
        ulonglong2 bN = *(const ulonglong2*)&sB[2][k][h_off];

        fma2(aR[0][0], pa0, bR.x); fma2(aR[0][1], pa0, bR.y);
        fma2(aR[1][0], pa1, bR.x); fma2(aR[1][1], pa1, bR.y);
        fma2(aR[2][0], pa2, bR.x); fma2(aR[2][1], pa2, bR.y);
        fma2(aR[3][0], pa3, bR.x); fma2(aR[3][1], pa3, bR.y);

        fma2(aZ[0][0], pa0, bZ.x); fma2(aZ[0][1], pa0, bZ.y);
        fma2(aZ[1][0], pa1, bZ.x); fma2(aZ[1][1], pa1, bZ.y);
        fma2(aZ[2][0], pa2, bZ.x); fma2(aZ[2][1], pa2, bZ.y);
        fma2(aZ[3][0], pa3, bZ.x); fma2(aZ[3][1], pa3, bZ.y);

        fma2(aN[0][0], pa0, bN.x); fma2(aN[0][1], pa0, bN.y);
        fma2(aN[1][0], pa1, bN.x); fma2(aN[1][1], pa1, bN.y);
        fma2(aN[2][0], pa2, bN.x); fma2(aN[2][1], pa2, bN.y);
        fma2(aN[3][0], pa3, bN.x); fma2(aN[3][1], pa3, bN.y);
    }
}

__global__ void __launch_bounds__(NTH, 1)
gru_step_kernel(const float* __restrict__ curr, int t,
                const float* __restrict__ Wih, const float* __restrict__ Whh,
                const float* __restrict__ bih, const float* __restrict__ bhh) {
    __shared__ float sA[2][BKQ][36];
    __shared__ float sB[2][3][BKQ][68];

    const float* x_t    = curr + (size_t)t * B_ * WS_;
    const float* h_prev = g_hs + (size_t)t * B_ * H_;
    float*       h_out  = g_hs + (size_t)(t + 1) * B_ * H_;

    const int tid   = threadIdx.x;
    const int h0    = blockIdx.x * BH;
    const int m0    = blockIdx.y * BM;
    const int m_off = (tid >> 4) << 2;   // 0..28
    const int h_off = (tid & 15) << 2;   // 0..60

    ull aR[4][2], aZ[4][2], aN[4][2], aI[4][2];
#pragma unroll
    for (int i = 0; i < 4; i++) {
        aR[i][0] = aR[i][1] = 0ULL;
        aZ[i][0] = aZ[i][1] = 0ULL;
        aN[i][0] = aN[i][1] = 0ULL;
        aI[i][0] = aI[i][1] = 0ULL;
    }

    Stage st;

    // ---- Phase 0: recurrent GEMM over K = H (Whh) -> aR, aZ, aN ----
    fetch_stage(st, h_prev, H_, Whh, H_, 0, m0, h0, tid);
    store_stage(st, tid, sA[0], sB[0]);
    __syncthreads();
#pragma unroll 1
    for (int k0 = 0; k0 < H_; k0 += BKQ) {
        int buf = (k0 >> 4) & 1;
        bool more = (k0 + BKQ) < H_;
        if (more) fetch_stage(st, h_prev, H_, Whh, H_, k0 + BKQ, m0, h0, tid);
        compute_tile(sA[buf], sB[buf], m_off, h_off, aR, aZ, aN);
        if (more) store_stage(st, tid, sA[buf ^ 1], sB[buf ^ 1]);
        __syncthreads();
    }

    // ---- Phase 1: input GEMM over K = WS (Wih) -> aR, aZ, aI ----
    fetch_stage(st, x_t, WS_, Wih, WS_, 0, m0, h0, tid);
    store_stage(st, tid, sA[0], sB[0]);
    __syncthreads();
#pragma unroll 1
    for (int k0 = 0; k0 < WS_; k0 += BKQ) {
        int buf = (k0 >> 4) & 1;
        bool more = (k0 + BKQ) < WS_;
        if (more) fetch_stage(st, x_t, WS_, Wih, WS_, k0 + BKQ, m0, h0, tid);
        compute_tile(sA[buf], sB[buf], m_off, h_off, aR, aZ, aI);
        if (more) store_stage(st, tid, sA[buf ^ 1], sB[buf ^ 1]);
        __syncthreads();
    }

    // ---- Epilogue: GRU gates + blend ----
#pragma unroll
    for (int i = 0; i < 4; i++) {
        int m = m0 + m_off + i;
#pragma unroll
        for (int p = 0; p < 2; p++) {
            float gr[2], gz[2], gn[2], gi[2];
            up2(aR[i][p], gr[0], gr[1]);
            up2(aZ[i][p], gz[0], gz[1]);
            up2(aN[i][p], gn[0], gn[1]);
            up2(aI[i][p], gi[0], gi[1]);
#pragma unroll
            for (int q = 0; q < 2; q++) {
                int j = h0 + h_off + 2 * p + q;
                float pre_r = gr[q] + bih[j] + bhh[j];
                float pre_z = gz[q] + bih[H_ + j] + bhh[H_ + j];
                float hn    = gn[q] + bhh[2 * H_ + j];
                float inn   = gi[q] + bih[2 * H_ + j];
                float r = 1.f / (1.f + expf(-pre_r));
                float z = 1.f / (1.f + expf(-pre_z));
                float n = tanhf(inn + r * hn);
                float hp = h_prev[(size_t)m * H_ + j];
                h_out[(size_t)m * H_ + j] = (1.f - z) * n + z * hp;
            }
        }
    }
}

// ---------------- Output projection: preds[b][t] = hs[t+1][b] . Wo + bo ----------------

__global__ void pred_kernel(const float* __restrict__ Wo,
                            const float* __restrict__ bo,
                            float* __restrict__ out) {
    int gw = (blockIdx.x * blockDim.x + threadIdx.x) >> 5;
    int lane = threadIdx.x & 31;
    if (gw >= T_ * B_) return;
    int t = gw / B_, b = gw % B_;
    const float* h = g_hs + ((size_t)(t + 1) * B_ + b) * H_;
    float s = 0.f;
#pragma unroll 8
    for (int k = lane; k < H_; k += 32) s = fmaf(h[k], Wo[k], s);
#pragma unroll
    for (int o = 16; o; o >>= 1) s += __shfl_xor_sync(0xffffffffu, s, o);
    if (lane == 0) out[(size_t)b * T_ + t] = s + bo[0];
}

// ---------------- Launch ----------------

extern "C" void kernel_launch(void* const* d_in, const int* in_sizes, int n_in,
                              void* d_out, int out_size) {
    const float* lag  = (const float*)d_in[0];
    const float* curr = (const float*)d_in[1];
    const float* W1   = (const float*)d_in[2];
    const float* b1   = (const float*)d_in[3];
    const float* W2   = (const float*)d_in[4];
    const float* b2   = (const float*)d_in[5];
    const float* W3   = (const float*)d_in[6];
    const float* b3   = (const float*)d_in[7];
    const float* Wih  = (const float*)d_in[8];
    const float* Whh  = (const float*)d_in[9];
    const float* bih  = (const float*)d_in[10];
    const float* bhh  = (const float*)d_in[11];
    const float* Wo   = (const float*)d_in[12];
    const float* bo   = (const float*)d_in[13];
    float* out = (float*)d_out;

    enc1_kernel<<<(B_ * 64 + 255) / 256, 256>>>(lag, W1, b1);
    enc2_kernel<<<(B_ * LAT_ + 255) / 256, 256>>>(W2, b2);
    enc3_kernel<<<(B_ * H_ + 255) / 256, 256>>>(W3, b3);

    dim3 grid(H_ / BH, B_ / BM);   // (16, 8) = 128 CTAs
    for (int t = 0; t < T_; t++) {
        gru_step_kernel<<<grid, NTH>>>(curr, t, Wih, Whh, bih, bhh);
    }

    int warps = T_ * B_;
    pred_kernel<<<(warps * 32 + 255) / 256, 256>>>(Wo, bo, out);
}

// round 17
// speedup vs baseline: 2.6615x; 2.6598x over previous
#include <cuda_runtime.h>
#include <cuda_bf16.h>
#include <math.h>
#include <stdint.h>

typedef unsigned int u32;

#define B_   256
#define T_   168
#define LAG_ 168
#define LAT_ 128
#define WS_  64
#define H_   1024

#define KTOT 1088         // H + WS
#define NCH  17           // 17 chunks of 64
#define NTHR 256

// smem layout (bytes)
#define SA_B   144        // A row stride: 72 bf16
#define SB_B   144        // B row stride
#define A_IMG  9216       // 64 rows * 144
#define B_IMG  13824      // 96 rows * 144
#define A_BUF  (2 * A_IMG)     // hi + lo
#define B_BUF  (2 * B_IMG)
#define OFF_A  0u
#define OFF_B  (2u * A_BUF)               // 36864
#define OFF_PA (OFF_B + 2u * B_BUF)       // 92160
#define OFF_PI (OFF_PA + 64u * 100u * 4u) // 117760
#define SMEM_SZ (OFF_PI + 64u * 36u * 4u) // 126976

// Global scratch (plain row-major)
__device__ __nv_bfloat16 g_A[(size_t)(T_ + 1) * 2 * B_ * KTOT];   // [t][split][m][k]
__device__ __nv_bfloat16 g_Wt[(size_t)2 * 3 * H_ * KTOT];         // [split][gate*H+j][k]
__device__ float g_hs[(size_t)(T_ + 1) * B_ * H_];
__device__ float g_e1[B_ * 64];
__device__ float g_e2[B_ * LAT_];

// ---------- PTX helpers (base ISA only) ----------
__device__ __forceinline__ u32 smem_u32(const void* p) {
    u32 a;
    asm("{ .reg .u64 t; cvta.to.shared.u64 t, %1; cvt.u32.u64 %0, t; }" : "=r"(a) : "l"(p));
    return a;
}
__device__ __forceinline__ void cpasync16(u32 dst, const void* src) {
    asm volatile("cp.async.cg.shared.global [%0], [%1], 16;" :: "r"(dst), "l"(src));
}
__device__ __forceinline__ void cp_commit() {
    asm volatile("cp.async.commit_group;" ::: "memory");
}
template<int N>
__device__ __forceinline__ void cp_wait() {
    asm volatile("cp.async.wait_group %0;" :: "n"(N) : "memory");
}
__device__ __forceinline__ void ldsm4(u32 a, u32* r) {
    asm volatile("ldmatrix.sync.aligned.m8n8.x4.shared.b16 {%0,%1,%2,%3}, [%4];"
        : "=r"(r[0]), "=r"(r[1]), "=r"(r[2]), "=r"(r[3]) : "r"(a));
}
__device__ __forceinline__ void ldsm2(u32 a, u32* r) {
    asm volatile("ldmatrix.sync.aligned.m8n8.x2.shared.b16 {%0,%1}, [%2];"
        : "=r"(r[0]), "=r"(r[1]) : "r"(a));
}
__device__ __forceinline__ void hmma(float* d, const u32* a, const u32* b) {
    asm volatile("mma.sync.aligned.m16n8k16.row.col.f32.bf16.bf16.f32 "
        "{%0,%1,%2,%3}, {%4,%5,%6,%7}, {%8,%9}, {%0,%1,%2,%3};"
        : "+f"(d[0]), "+f"(d[1]), "+f"(d[2]), "+f"(d[3])
        : "r"(a[0]), "r"(a[1]), "r"(a[2]), "r"(a[3]), "r"(b[0]), "r"(b[1]));
}

// ---------- Encoder MLP ----------
__global__ void enc1_kernel(const float* __restrict__ lag, const float* __restrict__ W1,
                            const float* __restrict__ b1) {
    int idx = blockIdx.x * blockDim.x + threadIdx.x;
    if (idx >= B_ * 64) return;
    int b = idx >> 6, o = idx & 63;
    const float* lr = lag + (size_t)b * LAG_;
    const float* wr = W1 + (size_t)o * LAG_;
    float s = b1[o];
#pragma unroll 4
    for (int k = 0; k < LAG_; k++) s = fmaf(lr[k], wr[k], s);
    g_e1[idx] = (s >= 0.f) ? s : 0.01f * s;
}

__global__ void enc2_kernel(const float* __restrict__ W2, const float* __restrict__ b2) {
    int idx = blockIdx.x * blockDim.x + threadIdx.x;
    if (idx >= B_ * LAT_) return;
    int b = idx / LAT_, o = idx % LAT_;
    const float* er = g_e1 + (size_t)b * 64;
    const float* wr = W2 + (size_t)o * 64;
    float s = b2[o];
#pragma unroll 8
    for (int k = 0; k < 64; k++) s = fmaf(er[k], wr[k], s);
    g_e2[idx] = (s >= 0.f) ? s : 0.01f * s;
}

__global__ void enc3_kernel(const float* __restrict__ W3, const float* __restrict__ b3) {
    int idx = blockIdx.x * blockDim.x + threadIdx.x;
    if (idx >= B_ * H_) return;
    int b = idx >> 10, o = idx & (H_ - 1);
    const float* er = g_e2 + (size_t)b * LAT_;
    const float* wr = W3 + (size_t)o * LAT_;
    float s = b3[o];
#pragma unroll 8
    for (int k = 0; k < LAT_; k++) s = fmaf(er[k], wr[k], s);
    g_hs[idx] = s;
    __nv_bfloat16 hb = __float2bfloat16(s);
    __nv_bfloat16 lb = __float2bfloat16(s - __bfloat162float(hb));
    g_A[(size_t)b * KTOT + o] = hb;                              // t=0, split 0
    g_A[(size_t)(B_ * KTOT) + (size_t)b * KTOT + o] = lb;        // t=0, split 1
}

__global__ void xconv_kernel(const float* __restrict__ curr) {
    int idx = blockIdx.x * blockDim.x + threadIdx.x;
    if (idx >= T_ * B_ * WS_) return;
    int t = idx / (B_ * WS_);
    int r = idx % (B_ * WS_);
    int b = r / WS_, k = r % WS_;
    float v = curr[idx];
    __nv_bfloat16 hb = __float2bfloat16(v);
    __nv_bfloat16 lb = __float2bfloat16(v - __bfloat162float(hb));
    size_t base = ((size_t)t * 2) * B_ * KTOT + (size_t)b * KTOT + H_ + k;
    g_A[base] = hb;
    g_A[base + (size_t)B_ * KTOT] = lb;
}

__global__ void wprep_kernel(const float* __restrict__ Whh, const float* __restrict__ Wih) {
    int idx = blockIdx.x * blockDim.x + threadIdx.x;
    if (idx >= 3 * H_ * KTOT) return;
    int R = idx / KTOT, k = idx % KTOT;
    float v = (k < H_) ? Whh[(size_t)R * H_ + k] : Wih[(size_t)R * WS_ + (k - H_)];
    __nv_bfloat16 hb = __float2bfloat16(v);
    __nv_bfloat16 lb = __float2bfloat16(v - __bfloat162float(hb));
    g_Wt[(size_t)R * KTOT + k] = hb;
    g_Wt[(size_t)(3 * H_) * KTOT + (size_t)R * KTOT + k] = lb;
}

// ---------- GRU step: HMMA bf16, 3-term split ----------
// CTA: 64 rows x 32 j-cols (x3 gates = 96 B rows). grid (32 jt, 4 mb) = 128 CTAs.
// Warps: 8 = (mw 0..1) x (nw 0..3); warp tile 32 rows x 24 cols (3 n8 blocks).

__device__ __forceinline__ void issue_chunk(u32 sb, int buf, int t2, int c,
                                            int m0, int j0, int tid) {
#pragma unroll
    for (int l = 0; l < 10; l++) {
        int i = tid + (l << 8);
        if (i < 1024) {
            int s = i >> 9, r = (i >> 3) & 63, kk = i & 7;
            const __nv_bfloat16* src =
                g_A + ((size_t)(t2 + s) * B_ + (m0 + r)) * KTOT + c * 64 + kk * 8;
            u32 dst = sb + OFF_A + buf * A_BUF + s * A_IMG + r * SA_B + kk * 16;
            cpasync16(dst, src);
        } else {
            int i2 = i - 1024;                   // < 1536
            int s = (i2 >= 768) ? 1 : 0;
            int rem = i2 - s * 768;
            int r = rem >> 3, kk = rem & 7;      // r: 0..95
            int R = (r >> 5) * H_ + j0 + (r & 31);
            const __nv_bfloat16* src =
                g_Wt + ((size_t)s * 3 * H_ + R) * KTOT + c * 64 + kk * 8;
            u32 dst = sb + OFF_B + buf * B_BUF + s * B_IMG + r * SB_B + kk * 16;
            cpasync16(dst, src);
        }
    }
}

__global__ void __launch_bounds__(NTHR, 1)
gru_step(int t, const float* __restrict__ bih, const float* __restrict__ bhh) {
    extern __shared__ unsigned char sm[];
    u32 sb = smem_u32(sm);
    const int tid = threadIdx.x, lane = tid & 31, wid = tid >> 5;
    const int mw = wid & 1, nw = wid >> 1;        // mw: m-half, nw: 24-col group
    const int jt = blockIdx.x, mb = blockIdx.y;
    const int j0 = jt * 32, m0 = mb * 64;
    const int t2 = t * 2;

    float accA[24], accI[24];
#pragma unroll
    for (int i = 0; i < 24; i++) { accA[i] = 0.f; accI[i] = 0.f; }

    // per-lane ldmatrix byte offsets (within an image)
    const u32 aoff = (u32)(mw * 32 + (lane & 15)) * SA_B + (u32)((lane >> 4) << 3) * 2;
    const u32 b4off = (u32)(nw * 24 + (lane & 7) + ((lane >> 4) << 3)) * SB_B
                    + (u32)(((lane >> 3) & 1) << 4);
    const u32 b2off = (u32)(nw * 24 + 16 + (lane & 7)) * SB_B
                    + (u32)(((lane >> 3) & 1) << 4);

    issue_chunk(sb, 0, t2, 0, m0, j0, tid);
    cp_commit();

#pragma unroll 1
    for (int c = 0; c < NCH; c++) {
        int buf = c & 1;
        if (c < NCH - 1) {
            issue_chunk(sb, buf ^ 1, t2, c + 1, m0, j0, tid);
            cp_commit();
            cp_wait<1>();
        } else {
            cp_wait<0>();
        }
        __syncthreads();

        const u32 aB = sb + OFF_A + (u32)buf * A_BUF;
        const u32 bB = sb + OFF_B + (u32)buf * B_BUF;
        const bool xc = (c == NCH - 1);

#pragma unroll
        for (int k16 = 0; k16 < 4; k16++) {
            const u32 kb = (u32)k16 * 32;
            u32 a0h[4], a1h[4], a0l[4], a1l[4];
            ldsm4(aB + aoff + kb, a0h);
            ldsm4(aB + aoff + 16 * SA_B + kb, a1h);
            ldsm4(aB + A_IMG + aoff + kb, a0l);
            ldsm4(aB + A_IMG + aoff + 16 * SA_B + kb, a1l);
            u32 bh[6], bl[6];
            ldsm4(bB + b4off + kb, bh);
            ldsm2(bB + b2off + kb, bh + 4);
            ldsm4(bB + B_IMG + b4off + kb, bl);
            ldsm2(bB + B_IMG + b2off + kb, bl + 4);

#pragma unroll
            for (int mi = 0; mi < 2; mi++) {
                const u32* Ah = mi ? a1h : a0h;
                const u32* Al = mi ? a1l : a0l;
#pragma unroll
                for (int ni = 0; ni < 3; ni++) {
                    bool toI = xc && (3 * nw + ni >= 8);
                    float* d = toI ? &accI[(mi * 3 + ni) * 4] : &accA[(mi * 3 + ni) * 4];
                    hmma(d, Ah, bh + ni * 2);
                    hmma(d, Ah, bl + ni * 2);
                    hmma(d, Al, bh + ni * 2);
                }
            }
        }
        __syncthreads();
    }

    // stage gate preacts: preactA[64][100], preactI[64][36]
    float* pa = (float*)(sm + OFF_PA);
    float* pi = (float*)(sm + OFF_PI);
    {
        const int r0 = lane >> 2, c0 = (lane & 3) << 1;
#pragma unroll
        for (int mi = 0; mi < 2; mi++) {
#pragma unroll
            for (int ni = 0; ni < 3; ni++) {
                int blk = 3 * nw + ni;
                int row = mw * 32 + mi * 16 + r0;
                int col = blk * 8 + c0;
                const float* d = &accA[(mi * 3 + ni) * 4];
                pa[row * 100 + col]       = d[0];
                pa[row * 100 + col + 1]   = d[1];
                pa[(row + 8) * 100 + col]     = d[2];
                pa[(row + 8) * 100 + col + 1] = d[3];
                if (blk >= 8) {
                    int ci = (blk - 8) * 8 + c0;
                    const float* e = &accI[(mi * 3 + ni) * 4];
                    pi[row * 36 + ci]       = e[0];
                    pi[row * 36 + ci + 1]   = e[1];
                    pi[(row + 8) * 36 + ci]     = e[2];
                    pi[(row + 8) * 36 + ci + 1] = e[3];
                }
            }
        }
    }
    __syncthreads();

    // epilogue: gates + blend; write fp32 h and bf16 hi/lo images for t+1
    const float* hsrc = g_hs + (size_t)t * B_ * H_;
    float* hdst = g_hs + (size_t)(t + 1) * B_ * H_;
    __nv_bfloat16* aHi = g_A + (size_t)(t2 + 2) * B_ * KTOT;
    __nv_bfloat16* aLo = aHi + (size_t)B_ * KTOT;

#pragma unroll
    for (int l = 0; l < 8; l++) {
        int idx = tid + (l << 8);
        int m = idx >> 5, j = idx & 31;
        int jj = j0 + j;
        float pre_r = pa[m * 100 + j]      + bih[jj]           + bhh[jj];
        float pre_z = pa[m * 100 + 32 + j] + bih[H_ + jj]      + bhh[H_ + jj];
        float hn    = pa[m * 100 + 64 + j] + bhh[2 * H_ + jj];
        float inn   = pi[m * 36 + j]       + bih[2 * H_ + jj];
        float r = 1.f / (1.f + expf(-pre_r));
        float z = 1.f / (1.f + expf(-pre_z));
        float n = tanhf(inn + r * hn);
        float hp = hsrc[(size_t)(m0 + m) * H_ + jj];
        float hv = (1.f - z) * n + z * hp;
        hdst[(size_t)(m0 + m) * H_ + jj] = hv;
        __nv_bfloat16 hb = __float2bfloat16(hv);
        __nv_bfloat16 lb = __float2bfloat16(hv - __bfloat162float(hb));
        aHi[(size_t)(m0 + m) * KTOT + jj] = hb;
        aLo[(size_t)(m0 + m) * KTOT + jj] = lb;
    }
}

// ---------- Output projection ----------
__global__ void pred_kernel(const float* __restrict__ Wo, const float* __restrict__ bo,
                            float* __restrict__ out) {
    int gw = (blockIdx.x * blockDim.x + threadIdx.x) >> 5;
    int lane = threadIdx.x & 31;
    if (gw >= T_ * B_) return;
    int t = gw / B_, b = gw % B_;
    const float* h = g_hs + ((size_t)(t + 1) * B_ + b) * H_;
    float s = 0.f;
#pragma unroll 8
    for (int k = lane; k < H_; k += 32) s = fmaf(h[k], Wo[k], s);
#pragma unroll
    for (int o = 16; o; o >>= 1) s += __shfl_xor_sync(0xffffffffu, s, o);
    if (lane == 0) out[(size_t)b * T_ + t] = s + bo[0];
}

// ---------- Launch ----------
extern "C" void kernel_launch(void* const* d_in, const int* in_sizes, int n_in,
                              void* d_out, int out_size) {
    const float* lag  = (const float*)d_in[0];
    const float* curr = (const float*)d_in[1];
    const float* W1   = (const float*)d_in[2];
    const float* b1   = (const float*)d_in[3];
    const float* W2   = (const float*)d_in[4];
    const float* b2   = (const float*)d_in[5];
    const float* W3   = (const float*)d_in[6];
    const float* b3   = (const float*)d_in[7];
    const float* Wih  = (const float*)d_in[8];
    const float* Whh  = (const float*)d_in[9];
    const float* bih  = (const float*)d_in[10];
    const float* bhh  = (const float*)d_in[11];
    const float* Wo   = (const float*)d_in[12];
    const float* bo   = (const float*)d_in[13];
    float* out = (float*)d_out;

    cudaFuncSetAttribute(gru_step, cudaFuncAttributeMaxDynamicSharedMemorySize, SMEM_SZ);

    enc1_kernel<<<(B_ * 64 + 255) / 256, 256>>>(lag, W1, b1);
    enc2_kernel<<<(B_ * LAT_ + 255) / 256, 256>>>(W2, b2);
    enc3_kernel<<<(B_ * H_ + 255) / 256, 256>>>(W3, b3);
    xconv_kernel<<<(T_ * B_ * WS_ + 255) / 256, 256>>>(curr);
    wprep_kernel<<<(3 * H_ * KTOT + 255) / 256, 256>>>(Whh, Wih);

    dim3 grid(32, 4);   // 128 CTAs
    for (int t = 0; t < T_; t++) {
        gru_step<<<grid, NTHR, SMEM_SZ>>>(t, bih, bhh);
    }

    pred_kernel<<<(T_ * B_ * 32 + 255) / 256, 256>>>(Wo, bo, out);
}